// round 7
// baseline (speedup 1.0000x reference)
#include <cuda_runtime.h>
#include <math.h>
#include <float.h>

// Problem constants
#define NB 1024
#define LL 200
#define DD 128
#define KK 3
#define CAP_PAD 129
#define NEG_PAD (-65535.0f)

// Shared-memory layout (floats)
//   cap_s : [0, 25800)            200 x 129 fp32 tile of low_capsule[b]
//   W4    : [25800, 26600)        W packed [l][4] (k=0..2 + pad) ; reused as reduce scratch later
//   u4    : [26600, 27112)        u packed [d][4]
//   h4    : [27112, 27624)        high packed [e][4] ; aliased (with g4) as u-pass reduce scratch
//   g4    : [27624, 28136)        g packed [d][4]
#define SM_FLOATS 28136
#define SMEM_BYTES (SM_FLOATS * 4)

__device__ float g_B[KK * LL];          // working routing logits
__device__ float g_delta[3][KK * LL];   // per-iteration delta accumulators
__device__ float g_ST[DD * DD];         // S transposed: ST[e*128 + d] = S[d*128 + e]

// ---------------------------------------------------------------------------
// init: copy B_matrix into working buffer, zero deltas, build S^T
// grid 64 x 256
// ---------------------------------------------------------------------------
__global__ void routing_init_kernel(const float* __restrict__ Bin,
                                    const float* __restrict__ S)
{
    int idx = blockIdx.x * 256 + threadIdx.x;   // 0..16383
    int d = idx >> 7;
    int e = idx & 127;
    g_ST[e * DD + d] = S[idx];                  // coalesced read of S
    if (blockIdx.x == 0) {
        for (int t = threadIdx.x; t < KK * LL; t += 256) {
            g_B[t] = Bin[t];
            g_delta[0][t] = 0.f;
            g_delta[1][t] = 0.f;
            g_delta[2][t] = 0.f;
        }
    }
}

// ---------------------------------------------------------------------------
// update: B += delta[it]
// grid 1 x 600
// ---------------------------------------------------------------------------
__global__ void routing_update_kernel(int it)
{
    int t = threadIdx.x;
    if (t < KK * LL) g_B[t] += g_delta[it][t];
}

// ---------------------------------------------------------------------------
// One full routing iteration, fused per batch element:
//   W = softmax(mask ? B : NEG_PAD)               (warps 0..2)
//   u[k,d]   = sum_l W[k,l] * cap[b,l,d]          (cap staged in smem)
//   hraw[k,e]= sum_d u[k,d]  * S[d,e]             (S from global, coalesced)
//   high     = squash_over_k(hraw)  -> out
//   g[k,d]   = sum_e high[k,e] * ST[e,d]
//   delta[k,l] += sum_d g[k,d] * cap[b,l,d]       (atomicAdd, 600 addrs)
// grid 1024 x 256, 112544 B dynamic smem, 2 CTAs/SM
// ---------------------------------------------------------------------------
__global__ void __launch_bounds__(256, 2)
routing_iter_kernel(const float* __restrict__ cap,
                    const float* __restrict__ S,
                    const void*  __restrict__ seqp,
                    int it,
                    float* __restrict__ out)
{
    extern __shared__ float sm[];
    float* cap_s = sm;
    float* W4    = sm + 25800;
    float* u4    = sm + 26600;
    float* h4    = sm + 27112;
    float* g4    = sm + 27624;
    float* red1  = h4;    // 1024 floats (h4+g4), scratch for u-pass partials
    float* red2  = W4;    // 800 floats, scratch for high/g-pass partials (W dead by then)

    const int b    = blockIdx.x;
    const int tid  = threadIdx.x;
    const int warp = tid >> 5;
    const int lane = tid & 31;

    // ---- sequence length: robust to int32 vs int64 storage --------------
    int n;
    {
        const int* si = (const int*)seqp;
        if (si[1] == 0) n = (int)(((const long long*)seqp)[b]);   // int64 layout
        else            n = si[b];                                 // int32 layout
    }

    // ---- masked softmax over L for each of the 3 routing rows ------------
    if (warp < 3) {
        const int k = warp;
        float v[7];
        float mx = -FLT_MAX;
        #pragma unroll
        for (int i = 0; i < 7; i++) {
            int l = lane + 32 * i;
            float x = -FLT_MAX;
            if (l < LL) x = (l < n) ? g_B[k * LL + l] : NEG_PAD;
            v[i] = x;
            mx = fmaxf(mx, x);
        }
        #pragma unroll
        for (int off = 16; off; off >>= 1)
            mx = fmaxf(mx, __shfl_xor_sync(0xffffffffu, mx, off));
        float s = 0.f;
        #pragma unroll
        for (int i = 0; i < 7; i++) {
            int l = lane + 32 * i;
            float e = (l < LL) ? expf(v[i] - mx) : 0.f;
            v[i] = e;
            s += e;
        }
        #pragma unroll
        for (int off = 16; off; off >>= 1)
            s += __shfl_xor_sync(0xffffffffu, s, off);
        float inv = 1.f / s;
        #pragma unroll
        for (int i = 0; i < 7; i++) {
            int l = lane + 32 * i;
            if (l < LL) W4[l * 4 + k] = v[i] * inv;
        }
    }

    // ---- stage low_capsule[b] (200x128 fp32) into smem, pad 129 ----------
    {
        const float4* src = (const float4*)(cap + (size_t)b * (LL * DD));
        #pragma unroll
        for (int itx = 0; itx < 25; itx++) {
            int i = tid + itx * 256;          // 0..6399
            int l = i >> 5;
            int j = i & 31;
            float4 v = src[i];
            float* dst = cap_s + l * CAP_PAD + 4 * j;
            dst[0] = v.x; dst[1] = v.y; dst[2] = v.z; dst[3] = v.w;
        }
    }
    __syncthreads();

    // ---- u[k,d] = sum_l W[k,l] * cap[l,d] : (d, l-half) split ------------
    {
        const int e = tid & 127;
        const int half = tid >> 7;
        float a0 = 0.f, a1 = 0.f, a2 = 0.f;
        const int l0 = half * 100;
        const float*  cs = cap_s + l0 * CAP_PAD + e;
        const float4* wp = ((const float4*)W4) + l0;
        #pragma unroll 4
        for (int l = 0; l < 100; l++) {
            float4 w = wp[l];                 // broadcast LDS.128
            float  c = cs[l * CAP_PAD];       // conflict-free (pad 129)
            a0 = fmaf(w.x, c, a0);
            a1 = fmaf(w.y, c, a1);
            a2 = fmaf(w.z, c, a2);
        }
        red1[half * 384 +       e] = a0;
        red1[half * 384 + 128 + e] = a1;
        red1[half * 384 + 256 + e] = a2;
    }
    __syncthreads();
    // BUGFIX (R4): block has 256 threads, so a plain `if (tid < 384)` only
    // reduced k=0,1 and left u4[:,k=2] as garbage. Strided loop covers all 384.
    for (int t = tid; t < 384; t += 256) {
        float uv = red1[t] + red1[384 + t];
        int k = t >> 7;
        int d = t & 127;
        u4[d * 4 + k] = uv;
    }
    __syncthreads();

    // ---- hraw[k,e] = sum_d u[k,d] * S[d,e] : (e, d-half) split -----------
    {
        const int e = tid & 127;
        const int half = tid >> 7;
        float h0 = 0.f, h1 = 0.f, h2 = 0.f;
        const int d0 = half * 64;
        const float* Sp = S + e;
        #pragma unroll 8
        for (int d = d0; d < d0 + 64; d++) {
            float4 u = *(const float4*)(u4 + d * 4);   // broadcast
            float  s = Sp[d * DD];                     // coalesced global
            h0 = fmaf(u.x, s, h0);
            h1 = fmaf(u.y, s, h1);
            h2 = fmaf(u.z, s, h2);
        }
        red2[half * 384 +       e] = h0;
        red2[half * 384 + 128 + e] = h1;
        red2[half * 384 + 256 + e] = h2;
    }
    __syncthreads();

    // ---- squash over k (reference: norm over dim=1 = K), write output ----
    if (tid < 128) {
        const int e = tid;
        float h0 = red2[e]       + red2[384 + e];
        float h1 = red2[128 + e] + red2[512 + e];
        float h2 = red2[256 + e] + red2[640 + e];
        float sq = h0 * h0 + h1 * h1 + h2 * h2;
        float scale = (sq / (1.f + sq)) * rsqrtf(sq + 1e-9f);
        h0 *= scale; h1 *= scale; h2 *= scale;
        float* op = out + (size_t)b * (KK * DD) + e;
        op[0]      = h0;
        op[DD]     = h1;
        op[2 * DD] = h2;
        h4[e * 4 + 0] = h0;
        h4[e * 4 + 1] = h1;
        h4[e * 4 + 2] = h2;
    }
    __syncthreads();

    // ---- g[k,d] = sum_e high[k,e] * ST[e,d] : (d, e-half) split ----------
    {
        const int d = tid & 127;
        const int half = tid >> 7;
        float q0 = 0.f, q1 = 0.f, q2 = 0.f;
        const int e0 = half * 64;
        const float* STp = g_ST + d;
        #pragma unroll 8
        for (int e = e0; e < e0 + 64; e++) {
            float4 h = *(const float4*)(h4 + e * 4);   // broadcast
            float  s = STp[e * DD];                    // coalesced global
            q0 = fmaf(h.x, s, q0);
            q1 = fmaf(h.y, s, q1);
            q2 = fmaf(h.z, s, q2);
        }
        red2[half * 384 +       d] = q0;
        red2[half * 384 + 128 + d] = q1;
        red2[half * 384 + 256 + d] = q2;
    }
    __syncthreads();
    // BUGFIX (R4): same 256-thread coverage bug as the u reduction.
    for (int t = tid; t < 384; t += 256) {
        float gv = red2[t] + red2[384 + t];
        int k = t >> 7;
        int d = t & 127;
        g4[d * 4 + k] = gv;
    }
    __syncthreads();

    // ---- delta[k,l] += sum_d g[k,d] * cap[l,d] ---------------------------
    if (tid < LL) {
        const int l = tid;
        float d0 = 0.f, d1 = 0.f, d2 = 0.f;
        const float* cs = cap_s + l * CAP_PAD;
        #pragma unroll 8
        for (int d = 0; d < 128; d++) {
            float4 g = *(const float4*)(g4 + d * 4);   // broadcast
            float  c = cs[d];                          // conflict-free (pad 129)
            d0 = fmaf(g.x, c, d0);
            d1 = fmaf(g.y, c, d1);
            d2 = fmaf(g.z, c, d2);
        }
        float* dp = g_delta[it];
        atomicAdd(dp + l,          d0);
        atomicAdd(dp + LL + l,     d1);
        atomicAdd(dp + 2 * LL + l, d2);
    }
}

// ---------------------------------------------------------------------------
// kernel_launch
//   d_in[0] low_capsule  f32 [1024*200*128]
//   d_in[1] B_matrix     f32 [1*3*200]
//   d_in[2] S_matrix     f32 [128*128]
//   d_in[3] seq_len      int [1024] (int32 or int64 — detected at runtime)
//   d_out  high          f32 [1024*3*128]
// ---------------------------------------------------------------------------
extern "C" void kernel_launch(void* const* d_in, const int* in_sizes, int n_in,
                              void* d_out, int out_size)
{
    (void)in_sizes; (void)n_in; (void)out_size;
    const float* cap  = (const float*)d_in[0];
    const float* Bin  = (const float*)d_in[1];
    const float* S    = (const float*)d_in[2];
    const void*  seqp = d_in[3];
    float* out = (float*)d_out;

    cudaFuncSetAttribute(routing_iter_kernel,
                         cudaFuncAttributeMaxDynamicSharedMemorySize, SMEM_BYTES);

    routing_init_kernel<<<64, 256>>>(Bin, S);

    routing_iter_kernel<<<NB, 256, SMEM_BYTES>>>(cap, S, seqp, 0, out);
    routing_update_kernel<<<1, 600>>>(0);
    routing_iter_kernel<<<NB, 256, SMEM_BYTES>>>(cap, S, seqp, 1, out);
    routing_update_kernel<<<1, 600>>>(1);
    routing_iter_kernel<<<NB, 256, SMEM_BYTES>>>(cap, S, seqp, 2, out);
}